// round 13
// baseline (speedup 1.0000x reference)
#include <cuda_runtime.h>
#include <cstdint>
#include <cstddef>

#define D      128
#define TM     64
#define NT     256
#define HSTR   132        // padded smem row stride (floats)
#define BN_EPS 1e-5f

#define MAXN 100000
#define MAXE 1600000
#define MAXG 1024
#define SCHUNK 1024
#define SMAXB  128

// ---- device scratch (no allocations allowed) ----
__device__ int   g_idx64;
__device__ int   g_srcdst[2 * MAXE];      // [src..., dst...] as int32
__device__ int   g_batch[MAXN];
__device__ int   g_cnt[MAXN];             // per-node in-degree
__device__ int   g_off[MAXN];             // CSR row starts
__device__ int   g_cur[MAXN];             // running fill cursor
__device__ int   g_csr[MAXE];             // src ids grouped by dst
__device__ int   g_bsum[SMAXB];
__device__ float g_X[(size_t)MAXN * D];   // ping buffer
__device__ float g_H[(size_t)MAXN * D];   // pong buffer
__device__ float g_G[MAXG * D];           // pooled graph features

// ---- packed f32x2 helpers ----
__device__ __forceinline__ unsigned long long pack2(float a, float b) {
    unsigned long long r;
    asm("mov.b64 %0, {%1, %2};" : "=l"(r) : "f"(a), "f"(b));
    return r;
}
__device__ __forceinline__ void unpack2(unsigned long long p, float& a, float& b) {
    asm("mov.b64 {%0, %1}, %2;" : "=f"(a), "=f"(b) : "l"(p));
}
__device__ __forceinline__ void fma2(unsigned long long& acc,
                                     unsigned long long a, unsigned long long b) {
    asm("fma.rn.f32x2 %0, %1, %2, %0;" : "+l"(acc) : "l"(a), "l"(b));
}

// ---------------------------------------------------------------------------
// int64/int32 index detection + canonicalization + CSR build
// ---------------------------------------------------------------------------
__global__ void detect_kernel(const unsigned long long* __restrict__ ei, int E) {
    if (blockIdx.x == 0 && threadIdx.x == 0) {
        int n = (E < 64) ? E : 64;
        int is64 = 1;
        for (int i = 0; i < n; i++)
            if (ei[i] > 0xFFFFFFFFull) is64 = 0;
        g_idx64 = is64;
    }
}

__global__ void convert_kernel(const void* __restrict__ ei,
                               const void* __restrict__ batch,
                               int E, int N, float* __restrict__ gp, int GD) {
    int i = blockIdx.x * blockDim.x + threadIdx.x;
    int is64 = g_idx64;
    if (i < 2 * E)
        g_srcdst[i] = is64 ? (int)((const long long*)ei)[i]
                           : ((const int*)ei)[i];
    if (i < N) {
        g_batch[i] = is64 ? (int)((const long long*)batch)[i]
                          : ((const int*)batch)[i];
        g_cnt[i] = 0;
    }
    if (i < GD) gp[i] = 0.f;
}

__global__ void hist_kernel(int E) {
    int i = blockIdx.x * blockDim.x + threadIdx.x;
    if (i < E) atomicAdd(&g_cnt[g_srcdst[E + i]], 1);
}

__global__ __launch_bounds__(SCHUNK)
void scan_part(int N) {
    __shared__ int wsum[32];
    const int i = blockIdx.x * SCHUNK + threadIdx.x;
    int v = (i < N) ? g_cnt[i] : 0;
    const int lane = threadIdx.x & 31, w = threadIdx.x >> 5;
    #pragma unroll
    for (int d = 16; d > 0; d >>= 1) v += __shfl_down_sync(0xFFFFFFFFu, v, d);
    if (lane == 0) wsum[w] = v;
    __syncthreads();
    if (w == 0) {
        int s = wsum[lane];
        #pragma unroll
        for (int d = 16; d > 0; d >>= 1) s += __shfl_down_sync(0xFFFFFFFFu, s, d);
        if (lane == 0) g_bsum[blockIdx.x] = s;
    }
}

__global__ __launch_bounds__(SMAXB)
void scan_mid(int nb) {
    __shared__ int wsum[4];
    const int t = threadIdx.x;
    const int lane = t & 31, w = t >> 5;
    int v = (t < nb) ? g_bsum[t] : 0;
    int incl = v;
    #pragma unroll
    for (int d = 1; d < 32; d <<= 1) {
        int n = __shfl_up_sync(0xFFFFFFFFu, incl, d);
        if (lane >= d) incl += n;
    }
    if (lane == 31) wsum[w] = incl;
    __syncthreads();
    int base = 0;
    #pragma unroll
    for (int k = 0; k < 4; k++) if (k < w) base += wsum[k];
    if (t < nb) g_bsum[t] = base + incl - v;
}

__global__ __launch_bounds__(SCHUNK)
void scan_final(int N) {
    __shared__ int wsum[32];
    const int i = blockIdx.x * SCHUNK + threadIdx.x;
    const int lane = threadIdx.x & 31, w = threadIdx.x >> 5;
    int v = (i < N) ? g_cnt[i] : 0;
    int incl = v;
    #pragma unroll
    for (int d = 1; d < 32; d <<= 1) {
        int n = __shfl_up_sync(0xFFFFFFFFu, incl, d);
        if (lane >= d) incl += n;
    }
    if (lane == 31) wsum[w] = incl;
    __syncthreads();
    if (w == 0) {
        int s = wsum[lane];
        #pragma unroll
        for (int d = 1; d < 32; d <<= 1) {
            int n = __shfl_up_sync(0xFFFFFFFFu, s, d);
            if (lane >= d) s += n;
        }
        wsum[lane] = s;
    }
    __syncthreads();
    int off = g_bsum[blockIdx.x] + (w > 0 ? wsum[w - 1] : 0) + incl - v;
    if (i < N) { g_off[i] = off; g_cur[i] = off; }
}

__global__ void fill_kernel(int E) {
    int i = blockIdx.x * blockDim.x + threadIdx.x;
    if (i < E) {
        int s = g_srcdst[i];
        int d = g_srcdst[E + i];
        int pos = atomicAdd(&g_cur[d], 1);
        g_csr[pos] = s;
    }
}

// ---------------------------------------------------------------------------
// Fused GIN layer over a 64-row tile:
//   Phase A (GATHER): hs[r] = Xin[r] + sum_{j in nbr(r)} Xin[j]   (CSR gather)
//           (!GATHER): hs[r] = Xin[r]                             (head MLP)
//   Phase B: h1 = relu( BN( hs @ W1 + b1 ) )  -> written back into hs
//            out = hs @ W2 + b2  (+relu)      -> Xout rows, or pooled (POOL)
// GEMMs use packed fma.rn.f32x2: thread (tr,tc) owns rows tr*4..+3,
// col pairs 2*tc + 32*jp. smem = Ws(32KB) + hs(33KB) -> 2 blocks/SM.
// ---------------------------------------------------------------------------
template <bool GATHER, bool USE_BN, bool POOL, bool RELU2>
__global__ __launch_bounds__(NT, 2)
void layer_kernel(const float* __restrict__ Xin,
                  const float* __restrict__ W1, const float* __restrict__ b1,
                  const float* __restrict__ gamma, const float* __restrict__ beta,
                  const float* __restrict__ mean, const float* __restrict__ var,
                  const float* __restrict__ W2, const float* __restrict__ b2,
                  float* __restrict__ Xout,
                  float* __restrict__ gpool,
                  int M) {
    extern __shared__ float sm[];
    float* Ws = sm;                 // 64 x 128  (k-chunk of W)
    float* hs = sm + 64 * D;        // 64 x HSTR (input tile / hidden tile)

    const int tid = threadIdx.x;
    const int tr = tid >> 4;        // 0..15 -> rows tr*4 .. tr*4+3
    const int tc = tid & 15;        // 0..15 -> col pairs at 2*tc + 32*jp
    const int row0 = blockIdx.x * TM;

    // ---- Phase A: build input tile in hs ----
    if (GATHER) {
        const int wrp = tid >> 5, lane = tid & 31;
        const float4* Xv = (const float4*)Xin;
        #pragma unroll 1
        for (int i = 0; i < 8; i++) {
            const int r = wrp * 8 + i;
            const int grow = row0 + r;
            float4 a = make_float4(0.f, 0.f, 0.f, 0.f);
            if (grow < M) {
                a = __ldg(Xv + (size_t)grow * 32 + lane);
                const int off = g_off[grow];
                const int deg = g_cnt[grow];
                int k = 0;
                for (; k + 4 <= deg; k += 4) {
                    int j0 = __ldg(g_csr + off + k);
                    int j1 = __ldg(g_csr + off + k + 1);
                    int j2 = __ldg(g_csr + off + k + 2);
                    int j3 = __ldg(g_csr + off + k + 3);
                    float4 v0 = __ldg(Xv + (size_t)j0 * 32 + lane);
                    float4 v1 = __ldg(Xv + (size_t)j1 * 32 + lane);
                    float4 v2 = __ldg(Xv + (size_t)j2 * 32 + lane);
                    float4 v3 = __ldg(Xv + (size_t)j3 * 32 + lane);
                    a.x += v0.x; a.y += v0.y; a.z += v0.z; a.w += v0.w;
                    a.x += v1.x; a.y += v1.y; a.z += v1.z; a.w += v1.w;
                    a.x += v2.x; a.y += v2.y; a.z += v2.z; a.w += v2.w;
                    a.x += v3.x; a.y += v3.y; a.z += v3.z; a.w += v3.w;
                }
                for (; k < deg; k++) {
                    int j = __ldg(g_csr + off + k);
                    float4 v = __ldg(Xv + (size_t)j * 32 + lane);
                    a.x += v.x; a.y += v.y; a.z += v.z; a.w += v.w;
                }
            }
            *(float4*)(hs + r * HSTR + lane * 4) = a;
        }
    } else {
        const float4* src = (const float4*)Xin;
        #pragma unroll
        for (int i = 0; i < 8; i++) {
            int lin = i * NT + tid;
            int r = lin >> 5, c4 = lin & 31;
            int grow = row0 + r;
            float4 v = make_float4(0.f, 0.f, 0.f, 0.f);
            if (grow < M) v = __ldg(src + (size_t)grow * 32 + c4);
            *(float4*)(hs + r * HSTR + c4 * 4) = v;
        }
    }

    unsigned long long acc[4][4];
    #pragma unroll
    for (int r = 0; r < 4; r++)
        #pragma unroll
        for (int jp = 0; jp < 4; jp++) acc[r][jp] = 0ull;

    // ---- GEMM1: acc = hs @ W1 (packed f32x2) ----
    for (int g = 0; g < 2; ++g) {
        __syncthreads();   // hs ready / previous Ws chunk consumed
        const float4* wsrc = (const float4*)(W1 + g * 64 * D);
        #pragma unroll
        for (int i = 0; i < 8; i++)
            ((float4*)Ws)[i * NT + tid] = __ldg(wsrc + i * NT + tid);
        __syncthreads();
        #pragma unroll 8
        for (int k = 0; k < 64; k++) {
            int kk = g * 64 + k;
            unsigned long long wp[4], hp[4];
            #pragma unroll
            for (int jp = 0; jp < 4; jp++)
                wp[jp] = *(const unsigned long long*)(Ws + k * D + 2 * tc + 32 * jp);
            #pragma unroll
            for (int r = 0; r < 4; r++) {
                float h = hs[(tr * 4 + r) * HSTR + kk];
                hp[r] = pack2(h, h);
            }
            #pragma unroll
            for (int r = 0; r < 4; r++)
                #pragma unroll
                for (int jp = 0; jp < 4; jp++)
                    fma2(acc[r][jp], hp[r], wp[jp]);
        }
    }
    __syncthreads();   // all GEMM1 reads of hs complete before overwrite

    // ---- epilogue1: bias (+BN) + ReLU -> back into hs ----
    #pragma unroll
    for (int jp = 0; jp < 4; jp++) {
        int col = 2 * tc + 32 * jp;
        float b0 = __ldg(b1 + col), b1v = __ldg(b1 + col + 1);
        float sc0 = 1.f, sh0 = 0.f, sc1 = 1.f, sh1 = 0.f;
        if (USE_BN) {
            sc0 = __ldg(gamma + col) * rsqrtf(__ldg(var + col) + BN_EPS);
            sh0 = __ldg(beta + col) - __ldg(mean + col) * sc0;
            sc1 = __ldg(gamma + col + 1) * rsqrtf(__ldg(var + col + 1) + BN_EPS);
            sh1 = __ldg(beta + col + 1) - __ldg(mean + col + 1) * sc1;
        }
        #pragma unroll
        for (int r = 0; r < 4; r++) {
            float v0, v1;
            unpack2(acc[r][jp], v0, v1);
            v0 += b0; v1 += b1v;
            if (USE_BN) { v0 = v0 * sc0 + sh0; v1 = v1 * sc1 + sh1; }
            v0 = fmaxf(v0, 0.f); v1 = fmaxf(v1, 0.f);
            *(float2*)(hs + (tr * 4 + r) * HSTR + col) = make_float2(v0, v1);
            acc[r][jp] = 0ull;
        }
    }

    // ---- GEMM2: acc = hs @ W2 (packed f32x2) ----
    for (int g = 0; g < 2; ++g) {
        __syncthreads();   // h1 writes visible / previous Ws chunk consumed
        const float4* wsrc = (const float4*)(W2 + g * 64 * D);
        #pragma unroll
        for (int i = 0; i < 8; i++)
            ((float4*)Ws)[i * NT + tid] = __ldg(wsrc + i * NT + tid);
        __syncthreads();
        #pragma unroll 8
        for (int k = 0; k < 64; k++) {
            int kk = g * 64 + k;
            unsigned long long wp[4], hp[4];
            #pragma unroll
            for (int jp = 0; jp < 4; jp++)
                wp[jp] = *(const unsigned long long*)(Ws + k * D + 2 * tc + 32 * jp);
            #pragma unroll
            for (int r = 0; r < 4; r++) {
                float h = hs[(tr * 4 + r) * HSTR + kk];
                hp[r] = pack2(h, h);
            }
            #pragma unroll
            for (int r = 0; r < 4; r++)
                #pragma unroll
                for (int jp = 0; jp < 4; jp++)
                    fma2(acc[r][jp], hp[r], wp[jp]);
        }
    }

    // ---- epilogue2 ----
    float outv[4][4][2];
    #pragma unroll
    for (int jp = 0; jp < 4; jp++) {
        int col = 2 * tc + 32 * jp;
        float b0 = __ldg(b2 + col), b1v = __ldg(b2 + col + 1);
        #pragma unroll
        for (int r = 0; r < 4; r++) {
            float v0, v1;
            unpack2(acc[r][jp], v0, v1);
            v0 += b0; v1 += b1v;
            if (RELU2) { v0 = fmaxf(v0, 0.f); v1 = fmaxf(v1, 0.f); }
            outv[r][jp][0] = v0; outv[r][jp][1] = v1;
        }
    }

    if (POOL) {
        int bid[4];
        #pragma unroll
        for (int r = 0; r < 4; r++) {
            int row = row0 + tr * 4 + r;
            bid[r] = (row < M) ? g_batch[row] : -1;
        }
        #pragma unroll
        for (int jp = 0; jp < 4; jp++) {
            int col = 2 * tc + 32 * jp;
            float s0 = 0.f, s1 = 0.f;
            int cur = -1;
            #pragma unroll
            for (int r = 0; r < 4; r++) {
                if (bid[r] < 0) continue;
                if (bid[r] != cur) {
                    if (cur >= 0) {
                        atomicAdd(gpool + (size_t)cur * D + col, s0);
                        atomicAdd(gpool + (size_t)cur * D + col + 1, s1);
                    }
                    cur = bid[r];
                    s0 = outv[r][jp][0]; s1 = outv[r][jp][1];
                } else {
                    s0 += outv[r][jp][0]; s1 += outv[r][jp][1];
                }
            }
            if (cur >= 0) {
                atomicAdd(gpool + (size_t)cur * D + col, s0);
                atomicAdd(gpool + (size_t)cur * D + col + 1, s1);
            }
        }
    } else {
        #pragma unroll
        for (int jp = 0; jp < 4; jp++) {
            int col = 2 * tc + 32 * jp;
            #pragma unroll
            for (int r = 0; r < 4; r++) {
                int row = row0 + tr * 4 + r;
                if (row < M)
                    *(float2*)(Xout + (size_t)row * D + col) =
                        make_float2(outv[r][jp][0], outv[r][jp][1]);
            }
        }
    }
}

// ---------------------------------------------------------------------------

extern "C" void kernel_launch(void* const* d_in, const int* in_sizes, int n_in,
                              void* d_out, int out_size) {
    const float* x    = (const float*)d_in[0];
    const void*  ei   = d_in[1];
    const void*  bat  = d_in[2];
    const float* cW1  = (const float*)d_in[3];
    const float* cb1  = (const float*)d_in[4];
    const float* gam  = (const float*)d_in[5];
    const float* bet  = (const float*)d_in[6];
    const float* mea  = (const float*)d_in[7];
    const float* var  = (const float*)d_in[8];
    const float* cW2  = (const float*)d_in[9];
    const float* cb2  = (const float*)d_in[10];
    const float* hW1  = (const float*)d_in[11];
    const float* hb1  = (const float*)d_in[12];
    const float* hW2  = (const float*)d_in[13];
    const float* hb2  = (const float*)d_in[14];

    const int N  = in_sizes[0] / D;
    const int E  = in_sizes[1] / 2;
    const int G  = out_size / D;
    const int GD = G * D;

    float *Xa, *Xb, *Gp;
    cudaGetSymbolAddress((void**)&Xa, g_X);
    cudaGetSymbolAddress((void**)&Xb, g_H);
    cudaGetSymbolAddress((void**)&Gp, g_G);

    const int smem = (64 * D + 64 * HSTR) * (int)sizeof(float);  // 66560 B
    cudaFuncSetAttribute(layer_kernel<true, true, false, true>,
                         cudaFuncAttributeMaxDynamicSharedMemorySize, smem);
    cudaFuncSetAttribute(layer_kernel<true, true, true, true>,
                         cudaFuncAttributeMaxDynamicSharedMemorySize, smem);
    cudaFuncSetAttribute(layer_kernel<false, false, false, false>,
                         cudaFuncAttributeMaxDynamicSharedMemorySize, smem);

    // ---- index canonicalization + CSR build ----
    detect_kernel<<<1, 32>>>((const unsigned long long*)ei, E);
    {
        int work = 2 * E;
        if (work < N) work = N;
        if (work < GD) work = GD;
        convert_kernel<<<(work + NT - 1) / NT, NT>>>(ei, bat, E, N, Gp, GD);
    }
    hist_kernel<<<(E + NT - 1) / NT, NT>>>(E);
    {
        const int nb = (N + SCHUNK - 1) / SCHUNK;
        scan_part<<<nb, SCHUNK>>>(N);
        scan_mid<<<1, SMAXB>>>(nb);
        scan_final<<<nb, SCHUNK>>>(N);
    }
    fill_kernel<<<(E + NT - 1) / NT, NT>>>(E);

    const int blocks = (N + TM - 1) / TM;

    // layer 0: x -> Xa     (gather + MLP fused)
    layer_kernel<true, true, false, true><<<blocks, NT, smem>>>(
        x, cW1, cb1, gam, bet, mea, var, cW2, cb2, Xa, nullptr, N);
    // layer 1: Xa -> Xb
    layer_kernel<true, true, false, true><<<blocks, NT, smem>>>(
        Xa, cW1 + (size_t)1 * D * D, cb1 + D, gam + D, bet + D, mea + D, var + D,
        cW2 + (size_t)1 * D * D, cb2 + D, Xb, nullptr, N);
    // layer 2: Xb -> pooled Gp (fused pool epilogue)
    layer_kernel<true, true, true, true><<<blocks, NT, smem>>>(
        Xb, cW1 + (size_t)2 * D * D, cb1 + 2 * D, gam + 2 * D, bet + 2 * D,
        mea + 2 * D, var + 2 * D, cW2 + (size_t)2 * D * D, cb2 + 2 * D,
        nullptr, Gp, N);

    // head MLP: relu(Gp @ hW1 + hb1) @ hW2 + hb2 -> d_out
    layer_kernel<false, false, false, false><<<(G + TM - 1) / TM, NT, smem>>>(
        Gp, hW1, hb1, nullptr, nullptr, nullptr, nullptr,
        hW2, hb2, (float*)d_out, nullptr, G);
}

// round 15
// speedup vs baseline: 1.0487x; 1.0487x over previous
#include <cuda_runtime.h>
#include <cstdint>
#include <cstddef>

#define D      128
#define TM     64
#define NT     256
#define HSTR   132        // padded smem row stride (floats)
#define BN_EPS 1e-5f

#define MAXN 100000
#define MAXE 1600000
#define MAXG 1024
#define SCHUNK 1024
#define SMAXB  128

// ---- device scratch (no allocations allowed) ----
__device__ int   g_idx64;
__device__ int   g_srcdst[2 * MAXE];      // [src..., dst...] as int32
__device__ int   g_batch[MAXN];
__device__ int   g_cnt[MAXN];             // per-node in-degree
__device__ int   g_off[MAXN];             // CSR row starts
__device__ int   g_cur[MAXN];             // running fill cursor
__device__ int   g_csr[MAXE];             // src ids grouped by dst
__device__ int   g_bsum[SMAXB];
__device__ float g_X[(size_t)MAXN * D];   // ping buffer (inter-layer features)
__device__ float g_H[(size_t)MAXN * D];   // pong buffer (aggregates)
__device__ float g_G[MAXG * D];           // pooled graph features

// ---- packed f32x2 helpers ----
__device__ __forceinline__ unsigned long long pack2(float a, float b) {
    unsigned long long r;
    asm("mov.b64 %0, {%1, %2};" : "=l"(r) : "f"(a), "f"(b));
    return r;
}
__device__ __forceinline__ void unpack2(unsigned long long p, float& a, float& b) {
    asm("mov.b64 {%0, %1}, %2;" : "=f"(a), "=f"(b) : "l"(p));
}
__device__ __forceinline__ void fma2(unsigned long long& acc,
                                     unsigned long long a, unsigned long long b) {
    asm("fma.rn.f32x2 %0, %1, %2, %0;" : "+l"(acc) : "l"(a), "l"(b));
}

// ---------------------------------------------------------------------------
// int64/int32 index detection + canonicalization + CSR build
// ---------------------------------------------------------------------------
__global__ void detect_kernel(const unsigned long long* __restrict__ ei, int E) {
    if (blockIdx.x == 0 && threadIdx.x == 0) {
        int n = (E < 64) ? E : 64;
        int is64 = 1;
        for (int i = 0; i < n; i++)
            if (ei[i] > 0xFFFFFFFFull) is64 = 0;
        g_idx64 = is64;
    }
}

__global__ void convert_kernel(const void* __restrict__ ei,
                               const void* __restrict__ batch,
                               int E, int N, float* __restrict__ gp, int GD) {
    int i = blockIdx.x * blockDim.x + threadIdx.x;
    int is64 = g_idx64;
    if (i < 2 * E)
        g_srcdst[i] = is64 ? (int)((const long long*)ei)[i]
                           : ((const int*)ei)[i];
    if (i < N) {
        g_batch[i] = is64 ? (int)((const long long*)batch)[i]
                          : ((const int*)batch)[i];
        g_cnt[i] = 0;
    }
    if (i < GD) gp[i] = 0.f;
}

__global__ void hist_kernel(int E) {
    int i = blockIdx.x * blockDim.x + threadIdx.x;
    if (i < E) atomicAdd(&g_cnt[g_srcdst[E + i]], 1);
}

__global__ __launch_bounds__(SCHUNK)
void scan_part(int N) {
    __shared__ int wsum[32];
    const int i = blockIdx.x * SCHUNK + threadIdx.x;
    int v = (i < N) ? g_cnt[i] : 0;
    const int lane = threadIdx.x & 31, w = threadIdx.x >> 5;
    #pragma unroll
    for (int d = 16; d > 0; d >>= 1) v += __shfl_down_sync(0xFFFFFFFFu, v, d);
    if (lane == 0) wsum[w] = v;
    __syncthreads();
    if (w == 0) {
        int s = wsum[lane];
        #pragma unroll
        for (int d = 16; d > 0; d >>= 1) s += __shfl_down_sync(0xFFFFFFFFu, s, d);
        if (lane == 0) g_bsum[blockIdx.x] = s;
    }
}

__global__ __launch_bounds__(SMAXB)
void scan_mid(int nb) {
    __shared__ int wsum[4];
    const int t = threadIdx.x;
    const int lane = t & 31, w = t >> 5;
    int v = (t < nb) ? g_bsum[t] : 0;
    int incl = v;
    #pragma unroll
    for (int d = 1; d < 32; d <<= 1) {
        int n = __shfl_up_sync(0xFFFFFFFFu, incl, d);
        if (lane >= d) incl += n;
    }
    if (lane == 31) wsum[w] = incl;
    __syncthreads();
    int base = 0;
    #pragma unroll
    for (int k = 0; k < 4; k++) if (k < w) base += wsum[k];
    if (t < nb) g_bsum[t] = base + incl - v;
}

__global__ __launch_bounds__(SCHUNK)
void scan_final(int N) {
    __shared__ int wsum[32];
    const int i = blockIdx.x * SCHUNK + threadIdx.x;
    const int lane = threadIdx.x & 31, w = threadIdx.x >> 5;
    int v = (i < N) ? g_cnt[i] : 0;
    int incl = v;
    #pragma unroll
    for (int d = 1; d < 32; d <<= 1) {
        int n = __shfl_up_sync(0xFFFFFFFFu, incl, d);
        if (lane >= d) incl += n;
    }
    if (lane == 31) wsum[w] = incl;
    __syncthreads();
    if (w == 0) {
        int s = wsum[lane];
        #pragma unroll
        for (int d = 1; d < 32; d <<= 1) {
            int n = __shfl_up_sync(0xFFFFFFFFu, s, d);
            if (lane >= d) s += n;
        }
        wsum[lane] = s;
    }
    __syncthreads();
    int off = g_bsum[blockIdx.x] + (w > 0 ? wsum[w - 1] : 0) + incl - v;
    if (i < N) { g_off[i] = off; g_cur[i] = off; }
}

__global__ void fill_kernel(int E) {
    int i = blockIdx.x * blockDim.x + threadIdx.x;
    if (i < E) {
        int s = g_srcdst[i];
        int d = g_srcdst[E + i];
        int pos = atomicAdd(&g_cur[d], 1);
        g_csr[pos] = s;
    }
}

// ---------------------------------------------------------------------------
// Gather aggregation: H[i] = X[i] + sum_{j in nbr(i)} X[j].
// One warp per node; at the LTS traffic floor (~65us/layer).
// ---------------------------------------------------------------------------
__global__ __launch_bounds__(NT)
void gather_kernel(const float* __restrict__ X, float* __restrict__ H, int N) {
    const int node = (blockIdx.x * NT + threadIdx.x) >> 5;
    const int lane = threadIdx.x & 31;
    if (node >= N) return;
    const float4* Xv = (const float4*)X;
    float4 a = __ldg(Xv + (size_t)node * 32 + lane);
    const int off = g_off[node];
    const int deg = g_cnt[node];
    int k = 0;
    for (; k + 4 <= deg; k += 4) {
        int j0 = __ldg(g_csr + off + k);
        int j1 = __ldg(g_csr + off + k + 1);
        int j2 = __ldg(g_csr + off + k + 2);
        int j3 = __ldg(g_csr + off + k + 3);
        float4 v0 = __ldg(Xv + (size_t)j0 * 32 + lane);
        float4 v1 = __ldg(Xv + (size_t)j1 * 32 + lane);
        float4 v2 = __ldg(Xv + (size_t)j2 * 32 + lane);
        float4 v3 = __ldg(Xv + (size_t)j3 * 32 + lane);
        a.x += v0.x; a.y += v0.y; a.z += v0.z; a.w += v0.w;
        a.x += v1.x; a.y += v1.y; a.z += v1.z; a.w += v1.w;
        a.x += v2.x; a.y += v2.y; a.z += v2.z; a.w += v2.w;
        a.x += v3.x; a.y += v3.y; a.z += v3.z; a.w += v3.w;
    }
    for (; k < deg; k++) {
        int j = __ldg(g_csr + off + k);
        float4 v = __ldg(Xv + (size_t)j * 32 + lane);
        a.x += v.x; a.y += v.y; a.z += v.z; a.w += v.w;
    }
    ((float4*)H)[(size_t)node * 32 + lane] = a;
}

// ---------------------------------------------------------------------------
// MLP over a 64-row tile, single hs buffer (h1 overwrites input tile):
//   h1 = relu( BN( hs @ W1 + b1 ) )  -> written back into hs
//   out = hs @ W2 + b2  (+relu)      -> Xout rows, or pooled (POOL)
// Packed fma.rn.f32x2; smem = Ws(32KB) + hs(33.8KB) -> 3 blocks/SM (24 warps).
// ---------------------------------------------------------------------------
template <bool USE_BN, bool POOL, bool RELU2>
__global__ __launch_bounds__(NT, 3)
void layer_kernel(const float* __restrict__ Hin,
                  const float* __restrict__ W1, const float* __restrict__ b1,
                  const float* __restrict__ gamma, const float* __restrict__ beta,
                  const float* __restrict__ mean, const float* __restrict__ var,
                  const float* __restrict__ W2, const float* __restrict__ b2,
                  float* __restrict__ Xout,
                  float* __restrict__ gpool,
                  int M) {
    extern __shared__ float sm[];
    float* Ws = sm;                 // 64 x 128  (k-chunk of W)
    float* hs = sm + 64 * D;        // 64 x HSTR (input tile / hidden tile)

    const int tid = threadIdx.x;
    const int tr = tid >> 4;        // 0..15 -> rows tr*4 .. tr*4+3
    const int tc = tid & 15;        // 0..15 -> col pairs at 2*tc + 32*jp
    const int row0 = blockIdx.x * TM;

    // ---- load input tile (zero-fill past M) ----
    {
        const float4* src = (const float4*)Hin;
        #pragma unroll
        for (int i = 0; i < 8; i++) {
            int lin = i * NT + tid;
            int r = lin >> 5, c4 = lin & 31;
            int grow = row0 + r;
            float4 v = make_float4(0.f, 0.f, 0.f, 0.f);
            if (grow < M) v = __ldg(src + (size_t)grow * 32 + c4);
            *(float4*)(hs + r * HSTR + c4 * 4) = v;
        }
    }

    unsigned long long acc[4][4];
    #pragma unroll
    for (int r = 0; r < 4; r++)
        #pragma unroll
        for (int jp = 0; jp < 4; jp++) acc[r][jp] = 0ull;

    // ---- GEMM1: acc = hs @ W1 (packed f32x2) ----
    for (int g = 0; g < 2; ++g) {
        __syncthreads();   // hs ready / previous Ws chunk consumed
        const float4* wsrc = (const float4*)(W1 + g * 64 * D);
        #pragma unroll
        for (int i = 0; i < 8; i++)
            ((float4*)Ws)[i * NT + tid] = __ldg(wsrc + i * NT + tid);
        __syncthreads();
        #pragma unroll 8
        for (int k = 0; k < 64; k++) {
            int kk = g * 64 + k;
            unsigned long long wp[4], hp[4];
            #pragma unroll
            for (int jp = 0; jp < 4; jp++)
                wp[jp] = *(const unsigned long long*)(Ws + k * D + 2 * tc + 32 * jp);
            #pragma unroll
            for (int r = 0; r < 4; r++) {
                float h = hs[(tr * 4 + r) * HSTR + kk];
                hp[r] = pack2(h, h);
            }
            #pragma unroll
            for (int r = 0; r < 4; r++)
                #pragma unroll
                for (int jp = 0; jp < 4; jp++)
                    fma2(acc[r][jp], hp[r], wp[jp]);
        }
    }
    __syncthreads();   // all GEMM1 reads of hs complete before overwrite

    // ---- epilogue1: bias (+BN) + ReLU -> back into hs ----
    #pragma unroll
    for (int jp = 0; jp < 4; jp++) {
        int col = 2 * tc + 32 * jp;
        float b0 = __ldg(b1 + col), b1v = __ldg(b1 + col + 1);
        float sc0 = 1.f, sh0 = 0.f, sc1 = 1.f, sh1 = 0.f;
        if (USE_BN) {
            sc0 = __ldg(gamma + col) * rsqrtf(__ldg(var + col) + BN_EPS);
            sh0 = __ldg(beta + col) - __ldg(mean + col) * sc0;
            sc1 = __ldg(gamma + col + 1) * rsqrtf(__ldg(var + col + 1) + BN_EPS);
            sh1 = __ldg(beta + col + 1) - __ldg(mean + col + 1) * sc1;
        }
        #pragma unroll
        for (int r = 0; r < 4; r++) {
            float v0, v1;
            unpack2(acc[r][jp], v0, v1);
            v0 += b0; v1 += b1v;
            if (USE_BN) { v0 = v0 * sc0 + sh0; v1 = v1 * sc1 + sh1; }
            v0 = fmaxf(v0, 0.f); v1 = fmaxf(v1, 0.f);
            *(float2*)(hs + (tr * 4 + r) * HSTR + col) = make_float2(v0, v1);
            acc[r][jp] = 0ull;
        }
    }

    // ---- GEMM2: acc = hs @ W2 (packed f32x2) ----
    for (int g = 0; g < 2; ++g) {
        __syncthreads();   // h1 writes visible / previous Ws chunk consumed
        const float4* wsrc = (const float4*)(W2 + g * 64 * D);
        #pragma unroll
        for (int i = 0; i < 8; i++)
            ((float4*)Ws)[i * NT + tid] = __ldg(wsrc + i * NT + tid);
        __syncthreads();
        #pragma unroll 8
        for (int k = 0; k < 64; k++) {
            int kk = g * 64 + k;
            unsigned long long wp[4], hp[4];
            #pragma unroll
            for (int jp = 0; jp < 4; jp++)
                wp[jp] = *(const unsigned long long*)(Ws + k * D + 2 * tc + 32 * jp);
            #pragma unroll
            for (int r = 0; r < 4; r++) {
                float h = hs[(tr * 4 + r) * HSTR + kk];
                hp[r] = pack2(h, h);
            }
            #pragma unroll
            for (int r = 0; r < 4; r++)
                #pragma unroll
                for (int jp = 0; jp < 4; jp++)
                    fma2(acc[r][jp], hp[r], wp[jp]);
        }
    }

    // ---- epilogue2 ----
    if (POOL) {
        int bid[4];
        #pragma unroll
        for (int r = 0; r < 4; r++) {
            int row = row0 + tr * 4 + r;
            bid[r] = (row < M) ? g_batch[row] : -1;
        }
        #pragma unroll
        for (int jp = 0; jp < 4; jp++) {
            int col = 2 * tc + 32 * jp;
            float b0 = __ldg(b2 + col), b1v = __ldg(b2 + col + 1);
            float s0 = 0.f, s1 = 0.f;
            int cur = -1;
            #pragma unroll
            for (int r = 0; r < 4; r++) {
                if (bid[r] < 0) continue;
                float v0, v1;
                unpack2(acc[r][jp], v0, v1);
                v0 += b0; v1 += b1v;
                if (RELU2) { v0 = fmaxf(v0, 0.f); v1 = fmaxf(v1, 0.f); }
                if (bid[r] != cur) {
                    if (cur >= 0) {
                        atomicAdd(gpool + (size_t)cur * D + col, s0);
                        atomicAdd(gpool + (size_t)cur * D + col + 1, s1);
                    }
                    cur = bid[r];
                    s0 = v0; s1 = v1;
                } else {
                    s0 += v0; s1 += v1;
                }
            }
            if (cur >= 0) {
                atomicAdd(gpool + (size_t)cur * D + col, s0);
                atomicAdd(gpool + (size_t)cur * D + col + 1, s1);
            }
        }
    } else {
        #pragma unroll
        for (int jp = 0; jp < 4; jp++) {
            int col = 2 * tc + 32 * jp;
            float b0 = __ldg(b2 + col), b1v = __ldg(b2 + col + 1);
            #pragma unroll
            for (int r = 0; r < 4; r++) {
                int row = row0 + tr * 4 + r;
                float v0, v1;
                unpack2(acc[r][jp], v0, v1);
                v0 += b0; v1 += b1v;
                if (RELU2) { v0 = fmaxf(v0, 0.f); v1 = fmaxf(v1, 0.f); }
                if (row < M)
                    *(float2*)(Xout + (size_t)row * D + col) = make_float2(v0, v1);
            }
        }
    }
}

// ---------------------------------------------------------------------------

extern "C" void kernel_launch(void* const* d_in, const int* in_sizes, int n_in,
                              void* d_out, int out_size) {
    const float* x    = (const float*)d_in[0];
    const void*  ei   = d_in[1];
    const void*  bat  = d_in[2];
    const float* cW1  = (const float*)d_in[3];
    const float* cb1  = (const float*)d_in[4];
    const float* gam  = (const float*)d_in[5];
    const float* bet  = (const float*)d_in[6];
    const float* mea  = (const float*)d_in[7];
    const float* var  = (const float*)d_in[8];
    const float* cW2  = (const float*)d_in[9];
    const float* cb2  = (const float*)d_in[10];
    const float* hW1  = (const float*)d_in[11];
    const float* hb1  = (const float*)d_in[12];
    const float* hW2  = (const float*)d_in[13];
    const float* hb2  = (const float*)d_in[14];

    const int N  = in_sizes[0] / D;
    const int E  = in_sizes[1] / 2;
    const int G  = out_size / D;
    const int GD = G * D;

    float *Xa, *Hb, *Gp;
    cudaGetSymbolAddress((void**)&Xa, g_X);
    cudaGetSymbolAddress((void**)&Hb, g_H);
    cudaGetSymbolAddress((void**)&Gp, g_G);

    const int smem = (64 * D + 64 * HSTR) * (int)sizeof(float);  // 66560 B
    cudaFuncSetAttribute(layer_kernel<true, false, true>,
                         cudaFuncAttributeMaxDynamicSharedMemorySize, smem);
    cudaFuncSetAttribute(layer_kernel<true, true, true>,
                         cudaFuncAttributeMaxDynamicSharedMemorySize, smem);
    cudaFuncSetAttribute(layer_kernel<false, false, false>,
                         cudaFuncAttributeMaxDynamicSharedMemorySize, smem);

    // ---- index canonicalization + CSR build ----
    detect_kernel<<<1, 32>>>((const unsigned long long*)ei, E);
    {
        int work = 2 * E;
        if (work < N) work = N;
        if (work < GD) work = GD;
        convert_kernel<<<(work + NT - 1) / NT, NT>>>(ei, bat, E, N, Gp, GD);
    }
    hist_kernel<<<(E + NT - 1) / NT, NT>>>(E);
    {
        const int nb = (N + SCHUNK - 1) / SCHUNK;
        scan_part<<<nb, SCHUNK>>>(N);
        scan_mid<<<1, SMAXB>>>(nb);
        scan_final<<<nb, SCHUNK>>>(N);
    }
    fill_kernel<<<(E + NT - 1) / NT, NT>>>(E);

    const int blocks = (N + TM - 1) / TM;
    const int gBlocks = (int)(((long long)N * 32 + NT - 1) / NT);

    for (int l = 0; l < 3; l++) {
        const float* xin = (l == 0) ? x : Xa;
        gather_kernel<<<gBlocks, NT>>>(xin, Hb, N);
        if (l < 2) {
            layer_kernel<true, false, true><<<blocks, NT, smem>>>(
                Hb, cW1 + (size_t)l * D * D, cb1 + l * D,
                gam + l * D, bet + l * D, mea + l * D, var + l * D,
                cW2 + (size_t)l * D * D, cb2 + l * D,
                Xa, nullptr, N);
        } else {
            layer_kernel<true, true, true><<<blocks, NT, smem>>>(
                Hb, cW1 + (size_t)l * D * D, cb1 + l * D,
                gam + l * D, bet + l * D, mea + l * D, var + l * D,
                cW2 + (size_t)l * D * D, cb2 + l * D,
                nullptr, Gp, N);
        }
    }

    // head MLP: relu(Gp @ hW1 + hb1) @ hW2 + hb2 -> d_out
    layer_kernel<false, false, false><<<(G + TM - 1) / TM, NT, smem>>>(
        Gp, hW1, hb1, nullptr, nullptr, nullptr, nullptr,
        hW2, hb2, (float*)d_out, nullptr, G);
}